// round 5
// baseline (speedup 1.0000x reference)
#include <cuda_runtime.h>
#include <cuda_bf16.h>

#define GDIM 128
#define NRAYS 2048
#define NSAMP 128
#define VD 28
#define BTHREADS 256
#define BWARPS 8
#define SAMP_PER_WARP (NSAMP / BWARPS)   // 16

// SH constants
#define Y00f 0.28209479177387814f
#define H3f  0.4886025119029199f
#define H15f 1.0925484305920792f
#define Q5f  0.31539156525252005f
#define Q15f 0.5462742152960396f

__global__ __launch_bounds__(BTHREADS, 4) void plenoxel_kernel(
    const float* __restrict__ grid,   // (G,G,G,28)
    const float* __restrict__ pos,    // (R,S,3)
    const float* __restrict__ dist,   // (R,S)
    const float* __restrict__ ang,    // (R,2)
    float* __restrict__ out)          // (R,3)
{
    const int r    = blockIdx.x;
    const int tid  = threadIdx.x;
    const int lane = tid & 31;
    const int wid  = tid >> 5;

    __shared__ float spos[NSAMP * 3];
    __shared__ float sdist[NSAMP];
    __shared__ float Ysh[9];
    __shared__ float att_s[NSAMP];
    __shared__ float weight_s[NSAMP];
    __shared__ float warp_att[4];
    __shared__ float warp_rgb[BWARPS][3];

    // Stage per-ray sample data coalesced
    for (int i = tid; i < NSAMP * 3; i += BTHREADS)
        spos[i] = pos[r * NSAMP * 3 + i];
    for (int i = tid; i < NSAMP; i += BTHREADS)
        sdist[i] = dist[r * NSAMP + i];
    if (tid == 0) {
        float th = ang[2 * r + 0];
        float ph = ang[2 * r + 1];
        float st, ct, sp, cp;
        sincosf(th, &st, &ct);
        sincosf(ph, &sp, &cp);
        float stcp = st * cp;
        float stsp = st * sp;
        Ysh[0] = Y00f;
        Ysh[1] = H3f * stsp;
        Ysh[2] = H3f * ct;
        Ysh[3] = H3f * stcp;
        Ysh[4] = H15f * stcp * stsp;
        Ysh[5] = H15f * stsp * ct;
        Ysh[6] = Q5f * (3.0f * ct * ct - 1.0f);
        Ysh[7] = H15f * stcp * ct;
        Ysh[8] = Q15f * (stcp * stcp - stsp * stsp);
    }
    __syncthreads();

    // Per-lane SH coefficient & color channel (lane = feature channel)
    float ycoef = 0.0f;
    int   q     = 3;                        // 3 = contributes to nothing
    if (lane >= 1 && lane < VD) {
        const int n = (lane - 1) % 9;
        q     = (lane - 1) / 9;
        ycoef = Ysh[n];
    }

    // ---- Phase 1: gather, keep feats in registers, compute att ----
    float f[SAMP_PER_WARP];

#pragma unroll
    for (int i = 0; i < SAMP_PER_WARP; i++) {
        const int s = wid * SAMP_PER_WARP + i;
        const float px = spos[3 * s + 0];
        const float py = spos[3 * s + 1];
        const float pz = spos[3 * s + 2];

        int ix = (int)floorf(px);
        int iy = (int)floorf(py);
        int iz = (int)floorf(pz);
        const float fx = px - (float)ix;
        const float fy = py - (float)iy;
        const float fz = pz - (float)iz;
        const int gmax = GDIM - 1;
        const int ix0 = min(max(ix, 0), gmax), ix1 = min(max(ix + 1, 0), gmax);
        const int iy0 = min(max(iy, 0), gmax), iy1 = min(max(iy + 1, 0), gmax);
        const int iz0 = min(max(iz, 0), gmax), iz1 = min(max(iz + 1, 0), gmax);

        const float wx0 = 1.0f - fx, wx1 = fx;
        const float wy0 = 1.0f - fy, wy1 = fy;
        const float wz0 = 1.0f - fz, wz1 = fz;

        const float w0 = wx0 * wy0 * wz0;
        const float w1 = wx0 * wy0 * wz1;
        const float w2 = wx0 * wy1 * wz0;
        const float w3 = wx0 * wy1 * wz1;
        const float w4 = wx1 * wy0 * wz0;
        const float w5 = wx1 * wy0 * wz1;
        const float w6 = wx1 * wy1 * wz0;
        const float w7 = wx1 * wy1 * wz1;

        const int b000 = ((ix0 * GDIM + iy0) * GDIM + iz0) * VD + lane;
        const int b001 = ((ix0 * GDIM + iy0) * GDIM + iz1) * VD + lane;
        const int b010 = ((ix0 * GDIM + iy1) * GDIM + iz0) * VD + lane;
        const int b011 = ((ix0 * GDIM + iy1) * GDIM + iz1) * VD + lane;
        const int b100 = ((ix1 * GDIM + iy0) * GDIM + iz0) * VD + lane;
        const int b101 = ((ix1 * GDIM + iy0) * GDIM + iz1) * VD + lane;
        const int b110 = ((ix1 * GDIM + iy1) * GDIM + iz0) * VD + lane;
        const int b111 = ((ix1 * GDIM + iy1) * GDIM + iz1) * VD + lane;

        float feats = 0.0f;
        if (lane < VD) {
            const float a0 = __ldg(grid + b000);
            const float a1 = __ldg(grid + b001);
            const float a2 = __ldg(grid + b010);
            const float a3 = __ldg(grid + b011);
            const float a4 = __ldg(grid + b100);
            const float a5 = __ldg(grid + b101);
            const float a6 = __ldg(grid + b110);
            const float a7 = __ldg(grid + b111);
            feats = w0*a0 + w1*a1 + w2*a2 + w3*a3
                  + w4*a4 + w5*a5 + w6*a6 + w7*a7;
        }
        f[i] = feats;

        const float sigma = __shfl_sync(0xffffffffu, feats, 0);
        if (lane == 0)
            att_s[s] = __expf(-sigma * sdist[s]);
    }
    __syncthreads();

    // ---- Phase 2: 128-wide inclusive scan of att -> weight in smem ----
    {
        float x = 0.0f, att = 0.0f;
        if (tid < NSAMP) {
            att = att_s[tid];
            x   = att;
        }
#pragma unroll
        for (int o = 1; o < 32; o <<= 1) {
            float ysh = __shfl_up_sync(0xffffffffu, x, o);
            if (lane >= o) x += ysh;
        }
        if (tid < NSAMP && lane == 31) warp_att[wid] = x;
        __syncthreads();

        if (tid < NSAMP) {
            float offset = 0.0f;
#pragma unroll
            for (int i = 0; i < 3; i++)
                if (i < wid) offset += warp_att[i];
            const float trans = x + offset;
            weight_s[tid] = trans * (1.0f - att);
        }
        __syncthreads();
    }

    // ---- Phase 3: accumulate weight * feats per lane (channel) ----
    float acc = 0.0f;
#pragma unroll
    for (int i = 0; i < SAMP_PER_WARP; i++) {
        const int s = wid * SAMP_PER_WARP + i;
        acc = fmaf(weight_s[s], f[i], acc);
    }

    // ---- Phase 4: project onto Y, one butterfly per warp ----
    const float t = acc * ycoef;
    float vr = (q == 0) ? t : 0.0f;
    float vg = (q == 1) ? t : 0.0f;
    float vb = (q == 2) ? t : 0.0f;
#pragma unroll
    for (int o = 16; o > 0; o >>= 1) {
        vr += __shfl_xor_sync(0xffffffffu, vr, o);
        vg += __shfl_xor_sync(0xffffffffu, vg, o);
        vb += __shfl_xor_sync(0xffffffffu, vb, o);
    }
    if (lane == 0) {
        warp_rgb[wid][0] = vr;
        warp_rgb[wid][1] = vg;
        warp_rgb[wid][2] = vb;
    }
    __syncthreads();

    if (tid == 0) {
        float R = 0.0f, Gg = 0.0f, B = 0.0f;
#pragma unroll
        for (int i = 0; i < BWARPS; i++) {
            R  += warp_rgb[i][0];
            Gg += warp_rgb[i][1];
            B  += warp_rgb[i][2];
        }
        out[3 * r + 0] = R;
        out[3 * r + 1] = Gg;
        out[3 * r + 2] = B;
    }
}

extern "C" void kernel_launch(void* const* d_in, const int* in_sizes, int n_in,
                              void* d_out, int out_size) {
    const float* grid = (const float*)d_in[0];
    const float* pos  = (const float*)d_in[1];
    const float* dst  = (const float*)d_in[2];
    const float* ang  = (const float*)d_in[3];
    float* out = (float*)d_out;
    plenoxel_kernel<<<NRAYS, BTHREADS>>>(grid, pos, dst, ang, out);
}